// round 3
// baseline (speedup 1.0000x reference)
#include <cuda_runtime.h>

#define N_NODES 100000
#define N_EDGES 1600000
#define F_IN    128
#define F_HID   128
#define F_OUT   64

// ---------------- static device scratch (no allocation allowed) ----------------
__device__ int   g_cnt[N_NODES];
__device__ int   g_off[N_NODES + 1];
__device__ int   g_cur[N_NODES];
__device__ int   g_srcs[N_EDGES];
__device__ float g_dinv[N_NODES];
__device__ __align__(16) float g_hs1 [N_NODES * F_HID];   // dinv-scaled x@W1
__device__ __align__(16) float g_agg1[N_NODES * F_HID];   // relu(layer1 out)
__device__ __align__(16) float g_hs2 [N_NODES * F_OUT];   // dinv-scaled agg1@W2

// ---------------- CSR build ----------------
__global__ void k_zero_cnt() {
    int i = blockIdx.x * blockDim.x + threadIdx.x;
    if (i < N_NODES) g_cnt[i] = 0;
}

// edge_index is int32 on device (JAX x64-disabled canonicalizes int64 -> int32).
// Unsigned guard: garbage indices are skipped instead of crashing.
__global__ void k_hist(const int* __restrict__ ei) {
    int e = blockIdx.x * blockDim.x + threadIdx.x;
    if (e < N_EDGES) {
        unsigned d = (unsigned)ei[N_EDGES + e];
        if (d < N_NODES) atomicAdd(&g_cnt[d], 1);
    }
}

// single-block scan: 1024 threads, each owns a contiguous segment
__global__ void k_scan() {
    __shared__ int sm[1024];
    const int t   = threadIdx.x;
    const int SEG = (N_NODES + 1023) / 1024;        // 98
    int s    = t * SEG;
    int epos = min(s + SEG, N_NODES);
    int sum = 0;
    for (int i = s; i < epos; i++) sum += g_cnt[i];
    sm[t] = sum;
    for (int d = 1; d < 1024; d <<= 1) {
        __syncthreads();
        int v = (t >= d) ? sm[t - d] : 0;
        __syncthreads();
        sm[t] += v;
    }
    __syncthreads();
    int run = sm[t] - sum;                           // exclusive
    for (int i = s; i < epos; i++) { g_off[i] = run; run += g_cnt[i]; }
    if (t == 1023) g_off[N_NODES] = sm[1023];
}

__global__ void k_dinv_cur() {
    int i = blockIdx.x * blockDim.x + threadIdx.x;
    if (i < N_NODES) {
        // deg = in-degree + 1 (self loop); always >= 1
        g_dinv[i] = rsqrtf((float)(g_cnt[i] + 1));
        g_cur[i]  = g_off[i];
    }
}

__global__ void k_fill(const int* __restrict__ ei) {
    int e = blockIdx.x * blockDim.x + threadIdx.x;
    if (e < N_EDGES) {
        unsigned d = (unsigned)ei[N_EDGES + e];
        unsigned s = (unsigned)ei[e];
        if (d < N_NODES && s < N_NODES) {
            int p = atomicAdd(&g_cur[d], 1);
            g_srcs[p] = (int)s;
        }
    }
}

// ---------------- SGEMM body with dinv-scaling epilogue ----------------
// C[r, :] = (A[r, :] @ B) * dinv[r];  Nc == BN (one block column covers full width)
template<int BM, int BN, int BK, int TM, int TN>
__device__ __forceinline__ void gemm_scale_body(
    const float* __restrict__ A, const float* __restrict__ B,
    float* __restrict__ C, int K, int Nc)
{
    constexpr int TX = BN / TN;
    constexpr int TY = BM / TM;
    constexpr int NT = TX * TY;
    __shared__ float As[BK][BM + 4];
    __shared__ float Bs[BK][BN];

    const int tid = threadIdx.x;
    const int tx  = tid % TX;
    const int ty  = tid / TX;
    const int rowBase = blockIdx.x * BM;

    float acc[TM][TN];
#pragma unroll
    for (int i = 0; i < TM; i++)
#pragma unroll
        for (int j = 0; j < TN; j++) acc[i][j] = 0.f;

    for (int kb = 0; kb < K; kb += BK) {
        // A tile (BM x BK), stored transposed into As
#pragma unroll
        for (int i = tid; i < BM * BK / 4; i += NT) {
            int r  = i / (BK / 4);
            int kq = (i % (BK / 4)) * 4;
            int gr = rowBase + r;
            float4 v = make_float4(0.f, 0.f, 0.f, 0.f);
            if (gr < N_NODES) v = *(const float4*)&A[gr * K + kb + kq];
            As[kq + 0][r] = v.x; As[kq + 1][r] = v.y;
            As[kq + 2][r] = v.z; As[kq + 3][r] = v.w;
        }
        // B tile (BK x BN), row-major
#pragma unroll
        for (int i = tid; i < BK * BN / 4; i += NT) {
            int k = (i * 4) / BN;
            int c = (i * 4) % BN;
            *(float4*)&Bs[k][c] = *(const float4*)&B[(kb + k) * Nc + c];
        }
        __syncthreads();
#pragma unroll
        for (int k = 0; k < BK; k++) {
            float a[TM], b[TN];
#pragma unroll
            for (int i = 0; i < TM; i += 4) *(float4*)&a[i] = *(const float4*)&As[k][ty * TM + i];
#pragma unroll
            for (int j = 0; j < TN; j += 4) *(float4*)&b[j] = *(const float4*)&Bs[k][tx * TN + j];
#pragma unroll
            for (int i = 0; i < TM; i++)
#pragma unroll
                for (int j = 0; j < TN; j++) acc[i][j] = fmaf(a[i], b[j], acc[i][j]);
        }
        __syncthreads();
    }
#pragma unroll
    for (int i = 0; i < TM; i++) {
        int gr = rowBase + ty * TM + i;
        if (gr < N_NODES) {
            float dv = g_dinv[gr];
#pragma unroll
            for (int j = 0; j < TN; j += 4) {
                float4 v;
                v.x = acc[i][j + 0] * dv;
                v.y = acc[i][j + 1] * dv;
                v.z = acc[i][j + 2] * dv;
                v.w = acc[i][j + 3] * dv;
                *(float4*)&C[gr * Nc + tx * TN + j] = v;
            }
        }
    }
}

// layer-1 GEMM: x (input param) @ W1 -> g_hs1
__global__ void k_gemm1(const float* __restrict__ x, const float* __restrict__ W1) {
    gemm_scale_body<128, 128, 16, 8, 8>(x, W1, g_hs1, F_IN, F_HID);
}

// layer-2 GEMM: g_agg1 @ W2 -> g_hs2
__global__ void k_gemm2(const float* __restrict__ W2) {
    gemm_scale_body<128, 64, 16, 8, 4>(g_agg1, W2, g_hs2, F_HID, F_OUT);
}

// ---------------- aggregation: warp per node, gather over CSR ----------------
// layer 1: width 128 (float4 per lane), +bias, relu
__global__ void k_agg1(const float* __restrict__ b1) {
    int w    = (blockIdx.x * blockDim.x + threadIdx.x) >> 5;
    int lane = threadIdx.x & 31;
    if (w >= N_NODES) return;
    const float4* hs = (const float4*)g_hs1;      // 32 float4 per row
    float4 acc = hs[w * 32 + lane];               // self-loop term (pre-scaled by dinv)
    int e  = g_off[w];
    int e1 = g_off[w + 1];
    for (; e + 3 < e1; e += 4) {
        int s0 = g_srcs[e + 0], s1 = g_srcs[e + 1];
        int s2 = g_srcs[e + 2], s3 = g_srcs[e + 3];
        float4 v0 = hs[s0 * 32 + lane];
        float4 v1 = hs[s1 * 32 + lane];
        float4 v2 = hs[s2 * 32 + lane];
        float4 v3 = hs[s3 * 32 + lane];
        acc.x += v0.x + v1.x + v2.x + v3.x;
        acc.y += v0.y + v1.y + v2.y + v3.y;
        acc.z += v0.z + v1.z + v2.z + v3.z;
        acc.w += v0.w + v1.w + v2.w + v3.w;
    }
    for (; e < e1; e++) {
        int s = g_srcs[e];
        float4 v = hs[s * 32 + lane];
        acc.x += v.x; acc.y += v.y; acc.z += v.z; acc.w += v.w;
    }
    float dv = g_dinv[w];
    float4 bb = ((const float4*)b1)[lane];
    float4 o;
    o.x = fmaxf(fmaf(acc.x, dv, bb.x), 0.f);
    o.y = fmaxf(fmaf(acc.y, dv, bb.y), 0.f);
    o.z = fmaxf(fmaf(acc.z, dv, bb.z), 0.f);
    o.w = fmaxf(fmaf(acc.w, dv, bb.w), 0.f);
    ((float4*)g_agg1)[w * 32 + lane] = o;
}

// layer 2: width 64 (float2 per lane), +bias, no relu, writes d_out
__global__ void k_agg2(const float* __restrict__ b2, float* __restrict__ out) {
    int w    = (blockIdx.x * blockDim.x + threadIdx.x) >> 5;
    int lane = threadIdx.x & 31;
    if (w >= N_NODES) return;
    const float2* hs = (const float2*)g_hs2;      // 32 float2 per row
    float2 acc = hs[w * 32 + lane];               // self-loop term
    int e  = g_off[w];
    int e1 = g_off[w + 1];
    for (; e + 3 < e1; e += 4) {
        int s0 = g_srcs[e + 0], s1 = g_srcs[e + 1];
        int s2 = g_srcs[e + 2], s3 = g_srcs[e + 3];
        float2 v0 = hs[s0 * 32 + lane];
        float2 v1 = hs[s1 * 32 + lane];
        float2 v2 = hs[s2 * 32 + lane];
        float2 v3 = hs[s3 * 32 + lane];
        acc.x += v0.x + v1.x + v2.x + v3.x;
        acc.y += v0.y + v1.y + v2.y + v3.y;
    }
    for (; e < e1; e++) {
        int s = g_srcs[e];
        float2 v = hs[s * 32 + lane];
        acc.x += v.x; acc.y += v.y;
    }
    float dv = g_dinv[w];
    float2 bb = ((const float2*)b2)[lane];
    float2 o;
    o.x = fmaf(acc.x, dv, bb.x);
    o.y = fmaf(acc.y, dv, bb.y);
    ((float2*)out)[w * 32 + lane] = o;
}

// ---------------- launcher ----------------
extern "C" void kernel_launch(void* const* d_in, const int* in_sizes, int n_in,
                              void* d_out, int out_size) {
    const float* x  = (const float*)d_in[0];
    const int*   ei = (const int*)d_in[1];
    const float* W1 = (const float*)d_in[2];
    const float* b1 = (const float*)d_in[3];
    const float* W2 = (const float*)d_in[4];
    const float* b2 = (const float*)d_in[5];
    float* out = (float*)d_out;

    const int NB_N = (N_NODES + 255) / 256;
    const int NB_E = (N_EDGES + 255) / 256;

    // CSR build
    k_zero_cnt<<<NB_N, 256>>>();
    k_hist<<<NB_E, 256>>>(ei);
    k_scan<<<1, 1024>>>();
    k_dinv_cur<<<NB_N, 256>>>();
    k_fill<<<NB_E, 256>>>(ei);

    // layer 1
    k_gemm1<<<(N_NODES + 127) / 128, 256>>>(x, W1);
    k_agg1<<<(N_NODES + 7) / 8, 256>>>(b1);

    // layer 2
    k_gemm2<<<(N_NODES + 127) / 128, 256>>>(W2);
    k_agg2<<<(N_NODES + 7) / 8, 256>>>(b2, out);
}

// round 4
// speedup vs baseline: 1.0920x; 1.0920x over previous
#include <cuda_runtime.h>

#define N_NODES 100000
#define N_EDGES 1600000
#define F_IN    128
#define F_HID   128
#define F_OUT   64

typedef unsigned long long u64;

// ---------------- packed f32x2 helpers (Blackwell double-rate fp32) ----------------
__device__ __forceinline__ u64 pack2(float lo, float hi) {
    u64 r; asm("mov.b64 %0, {%1, %2};" : "=l"(r) : "f"(lo), "f"(hi)); return r;
}
__device__ __forceinline__ void fma2(u64& d, u64 a, u64 b) {
    asm("fma.rn.f32x2 %0, %1, %2, %3;" : "=l"(d) : "l"(a), "l"(b), "l"(d));
}
__device__ __forceinline__ void unpack2(u64 v, float& lo, float& hi) {
    asm("mov.b64 {%0, %1}, %2;" : "=f"(lo), "=f"(hi) : "l"(v));
}

// ---------------- static device scratch (no allocation allowed) ----------------
__device__ int   g_cnt[N_NODES];
__device__ int   g_off[N_NODES + 1];
__device__ int   g_cur[N_NODES];
__device__ int   g_srcs[N_EDGES];
__device__ float g_dinv[N_NODES];
__device__ __align__(16) float g_hs1 [N_NODES * F_HID];   // dinv-scaled x@W1
__device__ __align__(16) float g_agg1[N_NODES * F_HID];   // relu(layer1 out)
__device__ __align__(16) float g_hs2 [N_NODES * F_OUT];   // dinv-scaled agg1@W2

// ---------------- CSR build ----------------
__global__ void k_zero_cnt() {
    int i = blockIdx.x * blockDim.x + threadIdx.x;
    if (i < N_NODES) g_cnt[i] = 0;
}

// edge_index is int32 on device (JAX x64-disabled canonicalizes int64 -> int32).
__global__ void k_hist(const int* __restrict__ ei) {
    int e = blockIdx.x * blockDim.x + threadIdx.x;
    if (e < N_EDGES) {
        unsigned d = (unsigned)ei[N_EDGES + e];
        if (d < N_NODES) atomicAdd(&g_cnt[d], 1);
    }
}

// single-block scan: 1024 threads, each owns a contiguous segment
__global__ void k_scan() {
    __shared__ int sm[1024];
    const int t   = threadIdx.x;
    const int SEG = (N_NODES + 1023) / 1024;        // 98
    int s    = t * SEG;
    int epos = min(s + SEG, N_NODES);
    int sum = 0;
    for (int i = s; i < epos; i++) sum += g_cnt[i];
    sm[t] = sum;
    for (int d = 1; d < 1024; d <<= 1) {
        __syncthreads();
        int v = (t >= d) ? sm[t - d] : 0;
        __syncthreads();
        sm[t] += v;
    }
    __syncthreads();
    int run = sm[t] - sum;                           // exclusive
    for (int i = s; i < epos; i++) { g_off[i] = run; run += g_cnt[i]; }
    if (t == 1023) g_off[N_NODES] = sm[1023];
}

__global__ void k_dinv_cur() {
    int i = blockIdx.x * blockDim.x + threadIdx.x;
    if (i < N_NODES) {
        g_dinv[i] = rsqrtf((float)(g_cnt[i] + 1));   // deg incl self-loop, >=1
        g_cur[i]  = g_off[i];
    }
}

__global__ void k_fill(const int* __restrict__ ei) {
    int e = blockIdx.x * blockDim.x + threadIdx.x;
    if (e < N_EDGES) {
        unsigned d = (unsigned)ei[N_EDGES + e];
        unsigned s = (unsigned)ei[e];
        if (d < N_NODES && s < N_NODES) {
            int p = atomicAdd(&g_cur[d], 1);
            g_srcs[p] = (int)s;
        }
    }
}

// ---------------- SGEMM body (packed f32x2 FMA) with dinv-scaling epilogue ----------------
// C[r, :] = (A[r, :] @ B) * dinv[r];  Nc == BN (one block column covers full width)
template<int BM, int BN, int BK, int TM, int TN>
__device__ __forceinline__ void gemm_scale_body(
    const float* __restrict__ A, const float* __restrict__ B,
    float* __restrict__ C, int K, int Nc)
{
    constexpr int TX  = BN / TN;
    constexpr int TY  = BM / TM;
    constexpr int NT  = TX * TY;
    constexpr int TN2 = TN / 2;
    __shared__ float As[BK][BM + 4];
    __shared__ __align__(16) float Bs[BK][BN];

    const int tid = threadIdx.x;
    const int tx  = tid % TX;
    const int ty  = tid / TX;
    const int rowBase = blockIdx.x * BM;

    u64 acc2[TM][TN2];
#pragma unroll
    for (int i = 0; i < TM; i++)
#pragma unroll
        for (int j = 0; j < TN2; j++) acc2[i][j] = 0ull;   // bit pattern == {0.f, 0.f}

    for (int kb = 0; kb < K; kb += BK) {
        // A tile (BM x BK), stored transposed into As
#pragma unroll
        for (int i = tid; i < BM * BK / 4; i += NT) {
            int r  = i / (BK / 4);
            int kq = (i % (BK / 4)) * 4;
            int gr = rowBase + r;
            float4 v = make_float4(0.f, 0.f, 0.f, 0.f);
            if (gr < N_NODES) v = *(const float4*)&A[gr * K + kb + kq];
            As[kq + 0][r] = v.x; As[kq + 1][r] = v.y;
            As[kq + 2][r] = v.z; As[kq + 3][r] = v.w;
        }
        // B tile (BK x BN), row-major
#pragma unroll
        for (int i = tid; i < BK * BN / 4; i += NT) {
            int k = (i * 4) / BN;
            int c = (i * 4) % BN;
            *(float4*)&Bs[k][c] = *(const float4*)&B[(kb + k) * Nc + c];
        }
        __syncthreads();
#pragma unroll
        for (int k = 0; k < BK; k++) {
            float a[TM];
#pragma unroll
            for (int i = 0; i < TM; i += 4) *(float4*)&a[i] = *(const float4*)&As[k][ty * TM + i];
            u64 aa[TM];
#pragma unroll
            for (int i = 0; i < TM; i++) aa[i] = pack2(a[i], a[i]);
            u64 bb[TN2];
#pragma unroll
            for (int j = 0; j < TN2; j++) bb[j] = *(const u64*)&Bs[k][tx * TN + 2 * j];
#pragma unroll
            for (int i = 0; i < TM; i++)
#pragma unroll
                for (int j = 0; j < TN2; j++) fma2(acc2[i][j], aa[i], bb[j]);
        }
        __syncthreads();
    }
#pragma unroll
    for (int i = 0; i < TM; i++) {
        int gr = rowBase + ty * TM + i;
        if (gr < N_NODES) {
            float dv = g_dinv[gr];
#pragma unroll
            for (int j = 0; j < TN2; j += 2) {
                float4 v;
                unpack2(acc2[i][j + 0], v.x, v.y);
                unpack2(acc2[i][j + 1], v.z, v.w);
                v.x *= dv; v.y *= dv; v.z *= dv; v.w *= dv;
                *(float4*)&C[gr * Nc + tx * TN + 2 * j] = v;
            }
        }
    }
}

// layer-1 GEMM: x (input param) @ W1 -> g_hs1
__global__ void k_gemm1(const float* __restrict__ x, const float* __restrict__ W1) {
    gemm_scale_body<128, 128, 16, 8, 8>(x, W1, g_hs1, F_IN, F_HID);
}

// layer-2 GEMM: g_agg1 @ W2 -> g_hs2
__global__ void k_gemm2(const float* __restrict__ W2) {
    gemm_scale_body<128, 64, 16, 8, 4>(g_agg1, W2, g_hs2, F_HID, F_OUT);
}

// ---------------- aggregation: warp per node, gather over CSR ----------------
// layer 1: width 128 (float4 per lane), +bias, relu
__global__ void k_agg1(const float* __restrict__ b1) {
    int w    = (blockIdx.x * blockDim.x + threadIdx.x) >> 5;
    int lane = threadIdx.x & 31;
    if (w >= N_NODES) return;
    const float4* hs = (const float4*)g_hs1;      // 32 float4 per row
    float4 acc = hs[w * 32 + lane];               // self-loop term (pre-scaled by dinv)
    int e  = g_off[w];
    int e1 = g_off[w + 1];
    for (; e + 7 < e1; e += 8) {
        int s[8];
#pragma unroll
        for (int q = 0; q < 8; q++) s[q] = g_srcs[e + q];
        float4 v[8];
#pragma unroll
        for (int q = 0; q < 8; q++) v[q] = hs[s[q] * 32 + lane];
#pragma unroll
        for (int q = 0; q < 8; q++) {
            acc.x += v[q].x; acc.y += v[q].y; acc.z += v[q].z; acc.w += v[q].w;
        }
    }
    for (; e < e1; e++) {
        int s = g_srcs[e];
        float4 v = hs[s * 32 + lane];
        acc.x += v.x; acc.y += v.y; acc.z += v.z; acc.w += v.w;
    }
    float dv = g_dinv[w];
    float4 bb = ((const float4*)b1)[lane];
    float4 o;
    o.x = fmaxf(fmaf(acc.x, dv, bb.x), 0.f);
    o.y = fmaxf(fmaf(acc.y, dv, bb.y), 0.f);
    o.z = fmaxf(fmaf(acc.z, dv, bb.z), 0.f);
    o.w = fmaxf(fmaf(acc.w, dv, bb.w), 0.f);
    ((float4*)g_agg1)[w * 32 + lane] = o;
}

// layer 2: width 64 (float2 per lane), +bias, no relu, writes d_out
__global__ void k_agg2(const float* __restrict__ b2, float* __restrict__ out) {
    int w    = (blockIdx.x * blockDim.x + threadIdx.x) >> 5;
    int lane = threadIdx.x & 31;
    if (w >= N_NODES) return;
    const float2* hs = (const float2*)g_hs2;      // 32 float2 per row
    float2 acc = hs[w * 32 + lane];               // self-loop term
    int e  = g_off[w];
    int e1 = g_off[w + 1];
    for (; e + 7 < e1; e += 8) {
        int s[8];
#pragma unroll
        for (int q = 0; q < 8; q++) s[q] = g_srcs[e + q];
        float2 v[8];
#pragma unroll
        for (int q = 0; q < 8; q++) v[q] = hs[s[q] * 32 + lane];
#pragma unroll
        for (int q = 0; q < 8; q++) { acc.x += v[q].x; acc.y += v[q].y; }
    }
    for (; e < e1; e++) {
        int s = g_srcs[e];
        float2 v = hs[s * 32 + lane];
        acc.x += v.x; acc.y += v.y;
    }
    float dv = g_dinv[w];
    float2 bb = ((const float2*)b2)[lane];
    float2 o;
    o.x = fmaf(acc.x, dv, bb.x);
    o.y = fmaf(acc.y, dv, bb.y);
    ((float2*)out)[w * 32 + lane] = o;
}

// ---------------- launcher ----------------
extern "C" void kernel_launch(void* const* d_in, const int* in_sizes, int n_in,
                              void* d_out, int out_size) {
    const float* x  = (const float*)d_in[0];
    const int*   ei = (const int*)d_in[1];
    const float* W1 = (const float*)d_in[2];
    const float* b1 = (const float*)d_in[3];
    const float* W2 = (const float*)d_in[4];
    const float* b2 = (const float*)d_in[5];
    float* out = (float*)d_out;

    const int NB_N = (N_NODES + 255) / 256;
    const int NB_E = (N_EDGES + 255) / 256;

    // CSR build
    k_zero_cnt<<<NB_N, 256>>>();
    k_hist<<<NB_E, 256>>>(ei);
    k_scan<<<1, 1024>>>();
    k_dinv_cur<<<NB_N, 256>>>();
    k_fill<<<NB_E, 256>>>(ei);

    // layer 1
    k_gemm1<<<(N_NODES + 127) / 128, 256>>>(x, W1);
    k_agg1<<<(N_NODES + 7) / 8, 256>>>(b1);

    // layer 2
    k_gemm2<<<(N_NODES + 127) / 128, 256>>>(W2);
    k_agg2<<<(N_NODES + 7) / 8, 256>>>(b2, out);
}